// round 1
// baseline (speedup 1.0000x reference)
#include <cuda_runtime.h>
#include <cstdint>
#include <cstddef>

// Problem constants (fixed by setup_inputs)
#define BB 16
#define SS 8192
#define DD 192
#define NH 16
#define HDIM 12
#define MTOT (BB*SS)   // 131072

// ---------------- scratch (device globals; allocations are forbidden) ----------------
__device__ float g_q[(size_t)MTOT * DD];
__device__ float g_k[(size_t)MTOT * DD];
__device__ float g_v[(size_t)MTOT * DD];
__device__ float g_attn[(size_t)MTOT * DD];

// ---------------- helpers ----------------
__device__ __forceinline__ float f2tf32(float x) {
    uint32_t u;
    asm("cvt.rna.tf32.f32 %0, %1;" : "=r"(u) : "f"(x));
    return __uint_as_float(u);
}

__device__ __forceinline__ void split4(const float4& v, float4& h, float4& l) {
    h.x = f2tf32(v.x); l.x = f2tf32(v.x - h.x);
    h.y = f2tf32(v.y); l.y = f2tf32(v.y - h.y);
    h.z = f2tf32(v.z); l.z = f2tf32(v.z - h.z);
    h.w = f2tf32(v.w); l.w = f2tf32(v.w - h.w);
}

__device__ __forceinline__ void mma8(float* c, const uint32_t a[4], uint32_t b0, uint32_t b1) {
    asm("mma.sync.aligned.m16n8k8.row.col.f32.tf32.tf32.f32 "
        "{%0,%1,%2,%3}, {%4,%5,%6,%7}, {%8,%9}, {%0,%1,%2,%3};"
        : "+f"(c[0]), "+f"(c[1]), "+f"(c[2]), "+f"(c[3])
        : "r"(a[0]), "r"(a[1]), "r"(a[2]), "r"(a[3]), "r"(b0), "r"(b1));
}

// =====================================================================================
// Kernel 1: QKV GEMM.  out[m,n] = sum_k x[m,k] * W[n,k]  (+bias, q prescaled)
// Grid: (1024, 9). blockIdx.y: tiles 0-2 -> Q, 3-5 -> K, 6-8 -> V. CTA tile 128x64.
// 3xtf32 for ~fp32 accuracy. Swizzled smem (c ^ ((r&7)<<2)) -> conflict-free frag LDS.
// =====================================================================================
__global__ __launch_bounds__(256) void k_qkv(
    const float* __restrict__ x,
    const float* __restrict__ Wq, const float* __restrict__ bq,
    const float* __restrict__ Wk, const float* __restrict__ bk,
    const float* __restrict__ Wv, const float* __restrict__ bv)
{
    extern __shared__ float sm[];
    float* sxh = sm;            // 128*32
    float* sxl = sm + 4096;     // 128*32
    float* swh = sm + 8192;     // 64*32
    float* swl = sm + 10240;    // 64*32  (total 12288 floats = 48KB)

    const int tid  = threadIdx.x;
    const int m0   = blockIdx.x * 128;
    const int by   = blockIdx.y;
    const int sel  = by / 3;                // 0=q, 1=k, 2=v
    const int nrow0 = (by % 3) * 64;        // row offset inside the 192-row weight
    const float* W = (sel == 0) ? Wq : (sel == 1) ? Wk : Wv;

    const int warp = tid >> 5, lane = tid & 31;
    const int wm = (warp >> 1) * 32;        // 4 m-warps
    const int wn = (warp & 1) * 32;         // 2 n-warps
    const int lr = lane >> 2;               // 0..7
    const int lc = lane & 3;                // 0..3

    float acc[2][4][4];
    #pragma unroll
    for (int a = 0; a < 2; a++)
        #pragma unroll
        for (int b = 0; b < 4; b++)
            #pragma unroll
            for (int c = 0; c < 4; c++) acc[a][b][c] = 0.f;

    for (int kt = 0; kt < 6; kt++) {
        __syncthreads();
        // stage x tile 128x32 (1024 float4)
        #pragma unroll
        for (int i = 0; i < 4; i++) {
            int id = i * 256 + tid;
            int r = id >> 3, cg = (id & 7) * 4;
            float4 v = *(const float4*)(x + (size_t)(m0 + r) * DD + kt * 32 + cg);
            float4 h, l; split4(v, h, l);
            int sc = cg ^ ((r & 7) << 2);
            *(float4*)(sxh + r * 32 + sc) = h;
            *(float4*)(sxl + r * 32 + sc) = l;
        }
        // stage W tile 64x32 (512 float4)
        #pragma unroll
        for (int i = 0; i < 2; i++) {
            int id = i * 256 + tid;
            int r = id >> 3, cg = (id & 7) * 4;
            float4 v = *(const float4*)(W + (size_t)(nrow0 + r) * DD + kt * 32 + cg);
            float4 h, l; split4(v, h, l);
            int sc = cg ^ ((r & 7) << 2);
            *(float4*)(swh + r * 32 + sc) = h;
            *(float4*)(swl + r * 32 + sc) = l;
        }
        __syncthreads();
        #pragma unroll
        for (int kk = 0; kk < 32; kk += 8) {
            uint32_t ah[2][4], al[2][4];
            #pragma unroll
            for (int im = 0; im < 2; im++) {
                int r0 = wm + im * 16 + lr;
                int r1 = r0 + 8;
                int c0 = kk + lc, c1 = c0 + 4;
                int s0 = (r0 & 7) << 2;     // (r1&7)==(r0&7)
                ah[im][0] = __float_as_uint(sxh[r0 * 32 + (c0 ^ s0)]);
                ah[im][1] = __float_as_uint(sxh[r1 * 32 + (c0 ^ s0)]);
                ah[im][2] = __float_as_uint(sxh[r0 * 32 + (c1 ^ s0)]);
                ah[im][3] = __float_as_uint(sxh[r1 * 32 + (c1 ^ s0)]);
                al[im][0] = __float_as_uint(sxl[r0 * 32 + (c0 ^ s0)]);
                al[im][1] = __float_as_uint(sxl[r1 * 32 + (c0 ^ s0)]);
                al[im][2] = __float_as_uint(sxl[r0 * 32 + (c1 ^ s0)]);
                al[im][3] = __float_as_uint(sxl[r1 * 32 + (c1 ^ s0)]);
            }
            #pragma unroll
            for (int jn = 0; jn < 4; jn++) {
                int nb = wn + jn * 8 + lr;
                int c0 = kk + lc, c1 = c0 + 4;
                int sb = (nb & 7) << 2;
                uint32_t bh0 = __float_as_uint(swh[nb * 32 + (c0 ^ sb)]);
                uint32_t bh1 = __float_as_uint(swh[nb * 32 + (c1 ^ sb)]);
                uint32_t bl0 = __float_as_uint(swl[nb * 32 + (c0 ^ sb)]);
                uint32_t bl1 = __float_as_uint(swl[nb * 32 + (c1 ^ sb)]);
                #pragma unroll
                for (int im = 0; im < 2; im++) {
                    mma8(acc[im][jn], ah[im], bl0, bl1);
                    mma8(acc[im][jn], al[im], bh0, bh1);
                    mma8(acc[im][jn], ah[im], bh0, bh1);
                }
            }
        }
    }

    // epilogue: bias (+ q prescale by 1/sqrt(12)) and store
    const float* bias = (sel == 0) ? bq : (sel == 1) ? bk : bv;
    float* dst = (sel == 0) ? g_q : (sel == 1) ? g_k : g_v;
    const float scale = (sel == 0) ? 0.28867513459481287f : 1.0f;
    #pragma unroll
    for (int im = 0; im < 2; im++) {
        #pragma unroll
        for (int jn = 0; jn < 4; jn++) {
            int r = m0 + wm + im * 16 + lr;
            int nloc = nrow0 + wn + jn * 8 + 2 * lc;
            float b0 = bias[nloc], b1 = bias[nloc + 1];
            float2 v0 = make_float2((acc[im][jn][0] + b0) * scale,
                                    (acc[im][jn][1] + b1) * scale);
            float2 v1 = make_float2((acc[im][jn][2] + b0) * scale,
                                    (acc[im][jn][3] + b1) * scale);
            *(float2*)(dst + (size_t)r * DD + nloc) = v0;
            *(float2*)(dst + (size_t)(r + 8) * DD + nloc) = v1;
        }
    }
}

// =====================================================================================
// Kernel 2: banded attention. One thread per (row m, head h). Window d in [-2,2].
// =====================================================================================
__global__ __launch_bounds__(256) void k_attn(const float* __restrict__ mask0)
{
    int g = blockIdx.x * 256 + threadIdx.x;
    int m = g >> 4;
    int h = g & 15;
    int i = m & (SS - 1);
    int b = m >> 13;

    const float* qp = g_q + (size_t)m * DD + h * HDIM;
    float q[12];
    #pragma unroll
    for (int j = 0; j < 3; j++) {
        float4 t = *(const float4*)(qp + 4 * j);
        q[4*j] = t.x; q[4*j+1] = t.y; q[4*j+2] = t.z; q[4*j+3] = t.w;
    }

    const float NEGINF = __int_as_float(0xff800000);
    float sc[5];
    bool val[5];
    #pragma unroll
    for (int dd = 0; dd < 5; dd++) {
        int d = dd - 2;
        int ik = i + d;
        bool v = (ik >= 0) && (ik < SS);
        val[dd] = v;
        float s = NEGINF;
        if (v) {
            const float* kp = g_k + (size_t)(m + d) * DD + h * HDIM;
            float a = 0.f;
            #pragma unroll
            for (int j = 0; j < 3; j++) {
                float4 t = *(const float4*)(kp + 4 * j);
                a += q[4*j] * t.x + q[4*j+1] * t.y + q[4*j+2] * t.z + q[4*j+3] * t.w;
            }
            float mk = mask0[b * SS + ik];
            s = a + ((mk != 0.f) ? -3.402823466e38f : 0.f);
        }
        sc[dd] = s;
    }
    float mx = sc[0];
    #pragma unroll
    for (int dd = 1; dd < 5; dd++) mx = fmaxf(mx, sc[dd]);
    float p[5], sum = 0.f;
    #pragma unroll
    for (int dd = 0; dd < 5; dd++) { p[dd] = __expf(sc[dd] - mx); sum += p[dd]; }
    float inv = 1.f / sum;
    if (mask0[b * SS + i] < 0.f) inv = 0.f;    // is_index_masked -> zero probs

    float ctx[12];
    #pragma unroll
    for (int j = 0; j < 12; j++) ctx[j] = 0.f;
    #pragma unroll
    for (int dd = 0; dd < 5; dd++) {
        if (val[dd]) {
            const float* vp = g_v + (size_t)(m + dd - 2) * DD + h * HDIM;
            #pragma unroll
            for (int j = 0; j < 3; j++) {
                float4 t = *(const float4*)(vp + 4 * j);
                ctx[4*j]   += p[dd] * t.x;
                ctx[4*j+1] += p[dd] * t.y;
                ctx[4*j+2] += p[dd] * t.z;
                ctx[4*j+3] += p[dd] * t.w;
            }
        }
    }
    float* op = g_attn + (size_t)m * DD + h * HDIM;
    #pragma unroll
    for (int j = 0; j < 3; j++) {
        float4 t;
        t.x = ctx[4*j]   * inv;
        t.y = ctx[4*j+1] * inv;
        t.z = ctx[4*j+2] * inv;
        t.w = ctx[4*j+3] * inv;
        *(float4*)(op + 4 * j) = t;
    }
}

// =====================================================================================
// Kernel 3: out = LN(attn @ Wo^T + bo + x). CTA: 64 rows x full 192 cols. Fused LN.
// =====================================================================================
__global__ __launch_bounds__(256) void k_out(
    const float* __restrict__ x, const float* __restrict__ Wo,
    const float* __restrict__ bo,
    const float* __restrict__ lng, const float* __restrict__ lnb,
    float* __restrict__ out)
{
    extern __shared__ float sm[];
    float* sah = sm;              // 64*32
    float* sal = sm + 2048;       // 64*32
    float* swh = sm + 4096;       // 192*32
    float* swl = sm + 10240;      // 192*32  (16384 floats = 64KB staging)
    float* sh  = sm;              // alias: 64 x 200 = 12800 floats (epilogue h)

    const int tid  = threadIdx.x;
    const int m0   = blockIdx.x * 64;
    const int warp = tid >> 5, lane = tid & 31;
    const int wm = (warp >> 1) * 16;   // 4 m-warps x 16 rows
    const int wn = (warp & 1) * 96;    // 2 n-warps x 96 cols
    const int lr = lane >> 2, lc = lane & 3;

    float acc[12][4];
    #pragma unroll
    for (int j = 0; j < 12; j++)
        #pragma unroll
        for (int c = 0; c < 4; c++) acc[j][c] = 0.f;

    for (int kt = 0; kt < 6; kt++) {
        __syncthreads();
        // stage attn tile 64x32 (512 float4)
        #pragma unroll
        for (int i = 0; i < 2; i++) {
            int id = i * 256 + tid;
            int r = id >> 3, cg = (id & 7) * 4;
            float4 v = *(const float4*)(g_attn + (size_t)(m0 + r) * DD + kt * 32 + cg);
            float4 h, l; split4(v, h, l);
            int sc = cg ^ ((r & 7) << 2);
            *(float4*)(sah + r * 32 + sc) = h;
            *(float4*)(sal + r * 32 + sc) = l;
        }
        // stage Wo tile 192x32 (1536 float4)
        #pragma unroll
        for (int i = 0; i < 6; i++) {
            int id = i * 256 + tid;
            int r = id >> 3, cg = (id & 7) * 4;
            float4 v = *(const float4*)(Wo + (size_t)r * DD + kt * 32 + cg);
            float4 h, l; split4(v, h, l);
            int sc = cg ^ ((r & 7) << 2);
            *(float4*)(swh + r * 32 + sc) = h;
            *(float4*)(swl + r * 32 + sc) = l;
        }
        __syncthreads();
        #pragma unroll
        for (int kk = 0; kk < 32; kk += 8) {
            int r0 = wm + lr, r1 = r0 + 8;
            int c0 = kk + lc, c1 = c0 + 4;
            int s0 = (r0 & 7) << 2;
            uint32_t ah[4], al[4];
            ah[0] = __float_as_uint(sah[r0 * 32 + (c0 ^ s0)]);
            ah[1] = __float_as_uint(sah[r1 * 32 + (c0 ^ s0)]);
            ah[2] = __float_as_uint(sah[r0 * 32 + (c1 ^ s0)]);
            ah[3] = __float_as_uint(sah[r1 * 32 + (c1 ^ s0)]);
            al[0] = __float_as_uint(sal[r0 * 32 + (c0 ^ s0)]);
            al[1] = __float_as_uint(sal[r1 * 32 + (c0 ^ s0)]);
            al[2] = __float_as_uint(sal[r0 * 32 + (c1 ^ s0)]);
            al[3] = __float_as_uint(sal[r1 * 32 + (c1 ^ s0)]);
            #pragma unroll
            for (int jn = 0; jn < 12; jn++) {
                int nb = wn + jn * 8 + lr;
                int sb = (nb & 7) << 2;
                uint32_t bh0 = __float_as_uint(swh[nb * 32 + (c0 ^ sb)]);
                uint32_t bh1 = __float_as_uint(swh[nb * 32 + (c1 ^ sb)]);
                uint32_t bl0 = __float_as_uint(swl[nb * 32 + (c0 ^ sb)]);
                uint32_t bl1 = __float_as_uint(swl[nb * 32 + (c1 ^ sb)]);
                mma8(acc[jn], ah, bl0, bl1);
                mma8(acc[jn], al, bh0, bh1);
                mma8(acc[jn], ah, bh0, bh1);
            }
        }
    }
    __syncthreads();

    // epilogue: h = acc + bo + x  -> sh (stride 200)
    #pragma unroll
    for (int jn = 0; jn < 12; jn++) {
        int rl = wm + lr;
        int col = wn + jn * 8 + 2 * lc;
        float b0 = bo[col], b1 = bo[col + 1];
        float2 xv0 = *(const float2*)(x + (size_t)(m0 + rl) * DD + col);
        float2 xv1 = *(const float2*)(x + (size_t)(m0 + rl + 8) * DD + col);
        sh[rl * 200 + col]           = acc[jn][0] + b0 + xv0.x;
        sh[rl * 200 + col + 1]       = acc[jn][1] + b1 + xv0.y;
        sh[(rl + 8) * 200 + col]     = acc[jn][2] + b0 + xv1.x;
        sh[(rl + 8) * 200 + col + 1] = acc[jn][3] + b1 + xv1.y;
    }
    __syncthreads();

    // LayerNorm: warp per row, 8 iterations
    #pragma unroll
    for (int it = 0; it < 8; it++) {
        int r = it * 8 + warp;
        float v[6]; float sum = 0.f, ssq = 0.f;
        #pragma unroll
        for (int j = 0; j < 6; j++) {
            v[j] = sh[r * 200 + j * 32 + lane];
            sum += v[j];
            ssq += v[j] * v[j];
        }
        #pragma unroll
        for (int o = 16; o > 0; o >>= 1) {
            sum += __shfl_xor_sync(0xffffffffu, sum, o);
            ssq += __shfl_xor_sync(0xffffffffu, ssq, o);
        }
        float mu  = sum * (1.f / 192.f);
        float var = ssq * (1.f / 192.f) - mu * mu;
        float rs  = rsqrtf(fmaxf(var, 0.f) + 1e-12f);
        #pragma unroll
        for (int j = 0; j < 6; j++) {
            int c = j * 32 + lane;
            out[(size_t)(m0 + r) * DD + c] = (v[j] - mu) * rs * lng[c] + lnb[c];
        }
    }
}

// =====================================================================================
extern "C" void kernel_launch(void* const* d_in, const int* in_sizes, int n_in,
                              void* d_out, int out_size)
{
    const float* x    = (const float*)d_in[0];
    const float* mask0= (const float*)d_in[1];
    const float* Wq   = (const float*)d_in[2];
    const float* bq   = (const float*)d_in[3];
    const float* Wk   = (const float*)d_in[4];
    const float* bk   = (const float*)d_in[5];
    const float* Wv   = (const float*)d_in[6];
    const float* bv   = (const float*)d_in[7];
    const float* Wo   = (const float*)d_in[8];
    const float* bo   = (const float*)d_in[9];
    const float* lng  = (const float*)d_in[10];
    const float* lnb  = (const float*)d_in[11];
    float* out = (float*)d_out;

    cudaFuncSetAttribute(k_qkv, cudaFuncAttributeMaxDynamicSharedMemorySize, 49152);
    cudaFuncSetAttribute(k_out, cudaFuncAttributeMaxDynamicSharedMemorySize, 65536);

    k_qkv<<<dim3(MTOT / 128, 9, 1), 256, 49152>>>(x, Wq, bq, Wk, bk, Wv, bv);
    k_attn<<<(MTOT * NH) / 256, 256>>>(mask0);
    k_out<<<MTOT / 64, 256, 65536>>>(x, Wo, bo, lng, lnb, out);
}

// round 2
// speedup vs baseline: 1.4772x; 1.4772x over previous
#include <cuda_runtime.h>
#include <cuda_bf16.h>
#include <cstdint>
#include <cstddef>

#define BB 16
#define SS 8192
#define DD 192
#define NH 16
#define HDIM 12
#define MTOT (BB*SS)   // 131072

// ---------------- scratch (device globals; allocations are forbidden) ----------------
__device__ float g_q[(size_t)MTOT * DD];
__device__ float g_k[(size_t)MTOT * DD];
__device__ float g_v[(size_t)MTOT * DD];
// pre-split bf16 hi/lo, packed 2 per word: [row][96 words]
__device__ __align__(16) uint32_t g_xh[(size_t)MTOT * 96];
__device__ __align__(16) uint32_t g_xl[(size_t)MTOT * 96];
__device__ __align__(16) uint32_t g_ah[(size_t)MTOT * 96];
__device__ __align__(16) uint32_t g_al[(size_t)MTOT * 96];
// weights: 4 mats (q,k,v,o) x 192 rows x 96 words
__device__ __align__(16) uint32_t g_wh[4 * 192 * 96];
__device__ __align__(16) uint32_t g_wl[4 * 192 * 96];

// ---------------- helpers ----------------
__device__ __forceinline__ uint32_t pack2(float a, float b) {
    __nv_bfloat162 t = __floats2bfloat162_rn(a, b);
    return reinterpret_cast<uint32_t&>(t);
}
__device__ __forceinline__ void split2(float a, float b, uint32_t& h, uint32_t& l) {
    float ah = __bfloat162float(__float2bfloat16_rn(a));
    float bh = __bfloat162float(__float2bfloat16_rn(b));
    h = pack2(ah, bh);
    l = pack2(a - ah, b - bh);
}
__device__ __forceinline__ void mma16(float* c, const uint32_t a[4], uint32_t b0, uint32_t b1) {
    asm volatile("mma.sync.aligned.m16n8k16.row.col.f32.bf16.bf16.f32 "
        "{%0,%1,%2,%3}, {%4,%5,%6,%7}, {%8,%9}, {%0,%1,%2,%3};"
        : "+f"(c[0]), "+f"(c[1]), "+f"(c[2]), "+f"(c[3])
        : "r"(a[0]), "r"(a[1]), "r"(a[2]), "r"(a[3]), "r"(b0), "r"(b1));
}
__device__ __forceinline__ void ldsm4(uint32_t* r, uint32_t saddr) {
    asm volatile("ldmatrix.sync.aligned.m8n8.x4.shared.b16 {%0,%1,%2,%3}, [%4];"
        : "=r"(r[0]), "=r"(r[1]), "=r"(r[2]), "=r"(r[3]) : "r"(saddr));
}
__device__ __forceinline__ void cpa16(uint32_t saddr, const void* g) {
    asm volatile("cp.async.cg.shared.global [%0], [%1], 16;" :: "r"(saddr), "l"(g));
}

// =====================================================================================
// split kernels (run once per launch; weights tiny, x 100MB)
// =====================================================================================
__global__ __launch_bounds__(256) void k_split_x(const float* __restrict__ x) {
    size_t f = (size_t)blockIdx.x * 256 + threadIdx.x;   // < MTOT*48
    float4 v = ((const float4*)x)[f];
    uint32_t h0, l0, h1, l1;
    split2(v.x, v.y, h0, l0);
    split2(v.z, v.w, h1, l1);
    ((uint2*)g_xh)[f] = make_uint2(h0, h1);
    ((uint2*)g_xl)[f] = make_uint2(l0, l1);
}
__global__ __launch_bounds__(256) void k_split_w(
    const float* __restrict__ Wq, const float* __restrict__ Wk,
    const float* __restrict__ Wv, const float* __restrict__ Wo) {
    int f = blockIdx.x * 256 + threadIdx.x;   // < 4*9216
    int mat = f / 9216, g = f - mat * 9216;
    const float* W = (mat == 0) ? Wq : (mat == 1) ? Wk : (mat == 2) ? Wv : Wo;
    float4 v = ((const float4*)W)[g];
    uint32_t h0, l0, h1, l1;
    split2(v.x, v.y, h0, l0);
    split2(v.z, v.w, h1, l1);
    ((uint2*)g_wh)[f] = make_uint2(h0, h1);
    ((uint2*)g_wl)[f] = make_uint2(l0, l1);
}

// =====================================================================================
// Kernel 1: QKV GEMM (bf16x3). CTA 64(M) x 192(N), K-tile 48, 2-stage cp.async.
// smem per buffer (words): A hi 64x28, A lo 64x28, B hi 192x28, B lo 192x28 = 14336
// =====================================================================================
__global__ __launch_bounds__(256, 2) void k_qkv(
    const float* __restrict__ bq, const float* __restrict__ bk, const float* __restrict__ bv)
{
    extern __shared__ uint32_t sm[];
    const uint32_t smbase = (uint32_t)__cvta_generic_to_shared(sm);
    const int tid = threadIdx.x;
    const int m0 = blockIdx.x * 64;
    const int sel = blockIdx.y;
    const int warp = tid >> 5, lane = tid & 31;
    const int wm = (warp >> 2) * 32, wn = (warp & 3) * 48;
    const int lr = lane >> 2, lc = lane & 3;
    const int group = lane >> 3, lrow = lane & 7;
    const int aoff = (lrow + ((group & 1) << 3)) * 28 + ((group >> 1) << 2);
    const int boff = (lrow + ((group >> 1) << 3)) * 28 + ((group & 1) << 2);
    const uint32_t* Wh = g_wh + sel * 18432;
    const uint32_t* Wl = g_wl + sel * 18432;

    float acc[2][6][4];
    #pragma unroll
    for (int a = 0; a < 2; a++)
        #pragma unroll
        for (int b = 0; b < 6; b++)
            #pragma unroll
            for (int c = 0; c < 4; c++) acc[a][b][c] = 0.f;

    auto stage = [&](int kt, int buf) {
        const int kw0 = kt * 24;
        const uint32_t base = buf * 14336;
        #pragma unroll
        for (int i = 0; i < 3; i++) {
            int id = i * 256 + tid;                 // 0..767
            int half = id >= 384;
            int j = id - (half ? 384 : 0);
            int r = j / 6, u = j - r * 6;
            const uint32_t* src = (half ? g_xl : g_xh) + (size_t)(m0 + r) * 96 + kw0 + u * 4;
            uint32_t sa = smbase + (base + (half ? 1792 : 0) + r * 28 + u * 4) * 4;
            cpa16(sa, src);
        }
        #pragma unroll
        for (int i = 0; i < 9; i++) {
            int id = i * 256 + tid;                 // 0..2303
            int half = id >= 1152;
            int j = id - (half ? 1152 : 0);
            int r = j / 6, u = j - r * 6;
            const uint32_t* src = (half ? Wl : Wh) + r * 96 + kw0 + u * 4;
            uint32_t sa = smbase + (base + 3584 + (half ? 5376 : 0) + r * 28 + u * 4) * 4;
            cpa16(sa, src);
        }
        asm volatile("cp.async.commit_group;");
    };

    auto compute = [&](int buf) {
        const uint32_t base = buf * 14336;
        #pragma unroll
        for (int s = 0; s < 3; s++) {
            const int kw = s * 8;
            uint32_t ah[2][4], al[2][4];
            #pragma unroll
            for (int im = 0; im < 2; im++) {
                uint32_t adr = smbase + (base + (wm + im * 16) * 28 + kw + aoff) * 4;
                ldsm4(ah[im], adr);
                ldsm4(al[im], adr + 1792 * 4);
            }
            uint32_t bh[3][4], bl[3][4];
            #pragma unroll
            for (int jp = 0; jp < 3; jp++) {
                uint32_t adr = smbase + (base + 3584 + (wn + jp * 16) * 28 + kw + boff) * 4;
                ldsm4(bh[jp], adr);
                ldsm4(bl[jp], adr + 5376 * 4);
            }
            #pragma unroll
            for (int im = 0; im < 2; im++)
                #pragma unroll
                for (int jp = 0; jp < 3; jp++) {
                    mma16(acc[im][2*jp],   ah[im], bl[jp][0], bl[jp][1]);
                    mma16(acc[im][2*jp],   al[im], bh[jp][0], bh[jp][1]);
                    mma16(acc[im][2*jp],   ah[im], bh[jp][0], bh[jp][1]);
                    mma16(acc[im][2*jp+1], ah[im], bl[jp][2], bl[jp][3]);
                    mma16(acc[im][2*jp+1], al[im], bh[jp][2], bh[jp][3]);
                    mma16(acc[im][2*jp+1], ah[im], bh[jp][2], bh[jp][3]);
                }
        }
    };

    stage(0, 0);
    for (int kt = 0; kt < 4; kt++) {
        if (kt < 3) {
            stage(kt + 1, (kt + 1) & 1);
            asm volatile("cp.async.wait_group 1;");
        } else {
            asm volatile("cp.async.wait_group 0;");
        }
        __syncthreads();
        compute(kt & 1);
        __syncthreads();
    }

    const float* bias = (sel == 0) ? bq : (sel == 1) ? bk : bv;
    float* dst = (sel == 0) ? g_q : (sel == 1) ? g_k : g_v;
    const float scale = (sel == 0) ? 0.28867513459481287f : 1.0f;
    #pragma unroll
    for (int im = 0; im < 2; im++)
        #pragma unroll
        for (int jn = 0; jn < 6; jn++) {
            int r = m0 + wm + im * 16 + lr;
            int col = wn + jn * 8 + 2 * lc;
            float b0 = bias[col], b1 = bias[col + 1];
            float2 v0 = make_float2((acc[im][jn][0] + b0) * scale,
                                    (acc[im][jn][1] + b1) * scale);
            float2 v1 = make_float2((acc[im][jn][2] + b0) * scale,
                                    (acc[im][jn][3] + b1) * scale);
            *(float2*)(dst + (size_t)r * DD + col) = v0;
            *(float2*)(dst + (size_t)(r + 8) * DD + col) = v1;
        }
}

// =====================================================================================
// Kernel 2: banded attention; writes pre-split bf16 attn (hi/lo packed words).
// =====================================================================================
__global__ __launch_bounds__(256) void k_attn(const float* __restrict__ mask0)
{
    int g = blockIdx.x * 256 + threadIdx.x;
    int m = g >> 4;
    int h = g & 15;
    int i = m & (SS - 1);
    int b = m >> 13;

    const float* qp = g_q + (size_t)m * DD + h * HDIM;
    float q[12];
    #pragma unroll
    for (int j = 0; j < 3; j++) {
        float4 t = *(const float4*)(qp + 4 * j);
        q[4*j] = t.x; q[4*j+1] = t.y; q[4*j+2] = t.z; q[4*j+3] = t.w;
    }

    const float NEGINF = __int_as_float(0xff800000);
    float sc[5];
    bool val[5];
    #pragma unroll
    for (int dd = 0; dd < 5; dd++) {
        int d = dd - 2;
        int ik = i + d;
        bool v = (ik >= 0) && (ik < SS);
        val[dd] = v;
        float s = NEGINF;
        if (v) {
            const float* kp = g_k + (size_t)(m + d) * DD + h * HDIM;
            float a = 0.f;
            #pragma unroll
            for (int j = 0; j < 3; j++) {
                float4 t = *(const float4*)(kp + 4 * j);
                a += q[4*j] * t.x + q[4*j+1] * t.y + q[4*j+2] * t.z + q[4*j+3] * t.w;
            }
            float mk = mask0[b * SS + ik];
            s = a + ((mk != 0.f) ? -3.402823466e38f : 0.f);
        }
        sc[dd] = s;
    }
    float mx = sc[0];
    #pragma unroll
    for (int dd = 1; dd < 5; dd++) mx = fmaxf(mx, sc[dd]);
    float p[5], sum = 0.f;
    #pragma unroll
    for (int dd = 0; dd < 5; dd++) { p[dd] = __expf(sc[dd] - mx); sum += p[dd]; }
    float inv = 1.f / sum;
    if (mask0[b * SS + i] < 0.f) inv = 0.f;

    float ctx[12];
    #pragma unroll
    for (int j = 0; j < 12; j++) ctx[j] = 0.f;
    #pragma unroll
    for (int dd = 0; dd < 5; dd++) {
        if (val[dd]) {
            const float* vp = g_v + (size_t)(m + dd - 2) * DD + h * HDIM;
            #pragma unroll
            for (int j = 0; j < 3; j++) {
                float4 t = *(const float4*)(vp + 4 * j);
                ctx[4*j]   += p[dd] * t.x;
                ctx[4*j+1] += p[dd] * t.y;
                ctx[4*j+2] += p[dd] * t.z;
                ctx[4*j+3] += p[dd] * t.w;
            }
        }
    }
    size_t ow = (size_t)m * 96 + h * 6;
    #pragma unroll
    for (int j = 0; j < 6; j++) {
        uint32_t hw, lw;
        split2(ctx[2*j] * inv, ctx[2*j+1] * inv, hw, lw);
        g_ah[ow + j] = hw;
        g_al[ow + j] = lw;
    }
}

// =====================================================================================
// Kernel 3: out = LN(attn @ Wo^T + bo + x). Same GEMM skeleton + fused LN epilogue.
// =====================================================================================
__global__ __launch_bounds__(256, 2) void k_out(
    const float* __restrict__ x, const float* __restrict__ bo,
    const float* __restrict__ lng, const float* __restrict__ lnb,
    float* __restrict__ out)
{
    extern __shared__ uint32_t sm[];
    const uint32_t smbase = (uint32_t)__cvta_generic_to_shared(sm);
    const int tid = threadIdx.x;
    const int m0 = blockIdx.x * 64;
    const int warp = tid >> 5, lane = tid & 31;
    const int wm = (warp >> 2) * 32, wn = (warp & 3) * 48;
    const int lr = lane >> 2, lc = lane & 3;
    const int group = lane >> 3, lrow = lane & 7;
    const int aoff = (lrow + ((group & 1) << 3)) * 28 + ((group >> 1) << 2);
    const int boff = (lrow + ((group >> 1) << 3)) * 28 + ((group & 1) << 2);
    const uint32_t* Wh = g_wh + 3 * 18432;
    const uint32_t* Wl = g_wl + 3 * 18432;

    float acc[2][6][4];
    #pragma unroll
    for (int a = 0; a < 2; a++)
        #pragma unroll
        for (int b = 0; b < 6; b++)
            #pragma unroll
            for (int c = 0; c < 4; c++) acc[a][b][c] = 0.f;

    auto stage = [&](int kt, int buf) {
        const int kw0 = kt * 24;
        const uint32_t base = buf * 14336;
        #pragma unroll
        for (int i = 0; i < 3; i++) {
            int id = i * 256 + tid;
            int half = id >= 384;
            int j = id - (half ? 384 : 0);
            int r = j / 6, u = j - r * 6;
            const uint32_t* src = (half ? g_al : g_ah) + (size_t)(m0 + r) * 96 + kw0 + u * 4;
            uint32_t sa = smbase + (base + (half ? 1792 : 0) + r * 28 + u * 4) * 4;
            cpa16(sa, src);
        }
        #pragma unroll
        for (int i = 0; i < 9; i++) {
            int id = i * 256 + tid;
            int half = id >= 1152;
            int j = id - (half ? 1152 : 0);
            int r = j / 6, u = j - r * 6;
            const uint32_t* src = (half ? Wl : Wh) + r * 96 + kw0 + u * 4;
            uint32_t sa = smbase + (base + 3584 + (half ? 5376 : 0) + r * 28 + u * 4) * 4;
            cpa16(sa, src);
        }
        asm volatile("cp.async.commit_group;");
    };

    auto compute = [&](int buf) {
        const uint32_t base = buf * 14336;
        #pragma unroll
        for (int s = 0; s < 3; s++) {
            const int kw = s * 8;
            uint32_t ah[2][4], al[2][4];
            #pragma unroll
            for (int im = 0; im < 2; im++) {
                uint32_t adr = smbase + (base + (wm + im * 16) * 28 + kw + aoff) * 4;
                ldsm4(ah[im], adr);
                ldsm4(al[im], adr + 1792 * 4);
            }
            uint32_t bh[3][4], bl[3][4];
            #pragma unroll
            for (int jp = 0; jp < 3; jp++) {
                uint32_t adr = smbase + (base + 3584 + (wn + jp * 16) * 28 + kw + boff) * 4;
                ldsm4(bh[jp], adr);
                ldsm4(bl[jp], adr + 5376 * 4);
            }
            #pragma unroll
            for (int im = 0; im < 2; im++)
                #pragma unroll
                for (int jp = 0; jp < 3; jp++) {
                    mma16(acc[im][2*jp],   ah[im], bl[jp][0], bl[jp][1]);
                    mma16(acc[im][2*jp],   al[im], bh[jp][0], bh[jp][1]);
                    mma16(acc[im][2*jp],   ah[im], bh[jp][0], bh[jp][1]);
                    mma16(acc[im][2*jp+1], ah[im], bl[jp][2], bl[jp][3]);
                    mma16(acc[im][2*jp+1], al[im], bh[jp][2], bh[jp][3]);
                    mma16(acc[im][2*jp+1], ah[im], bh[jp][2], bh[jp][3]);
                }
        }
    };

    stage(0, 0);
    for (int kt = 0; kt < 4; kt++) {
        if (kt < 3) {
            stage(kt + 1, (kt + 1) & 1);
            asm volatile("cp.async.wait_group 1;");
        } else {
            asm volatile("cp.async.wait_group 0;");
        }
        __syncthreads();
        compute(kt & 1);
        __syncthreads();
    }

    // epilogue: h = acc + bo + x -> smem (stride 200 floats), then LN
    float* sh = (float*)sm;
    #pragma unroll
    for (int im = 0; im < 2; im++)
        #pragma unroll
        for (int jn = 0; jn < 6; jn++) {
            int rl = wm + im * 16 + lr;
            int col = wn + jn * 8 + 2 * lc;
            float b0 = bo[col], b1 = bo[col + 1];
            float2 xv0 = *(const float2*)(x + (size_t)(m0 + rl) * DD + col);
            float2 xv1 = *(const float2*)(x + (size_t)(m0 + rl + 8) * DD + col);
            sh[rl * 200 + col]           = acc[im][jn][0] + b0 + xv0.x;
            sh[rl * 200 + col + 1]       = acc[im][jn][1] + b1 + xv0.y;
            sh[(rl + 8) * 200 + col]     = acc[im][jn][2] + b0 + xv1.x;
            sh[(rl + 8) * 200 + col + 1] = acc[im][jn][3] + b1 + xv1.y;
        }
    __syncthreads();

    #pragma unroll
    for (int it = 0; it < 8; it++) {
        int r = it * 8 + warp;
        float v[6]; float sum = 0.f, ssq = 0.f;
        #pragma unroll
        for (int j = 0; j < 6; j++) {
            v[j] = sh[r * 200 + j * 32 + lane];
            sum += v[j];
            ssq += v[j] * v[j];
        }
        #pragma unroll
        for (int o = 16; o > 0; o >>= 1) {
            sum += __shfl_xor_sync(0xffffffffu, sum, o);
            ssq += __shfl_xor_sync(0xffffffffu, ssq, o);
        }
        float mu  = sum * (1.f / 192.f);
        float var = ssq * (1.f / 192.f) - mu * mu;
        float rs  = rsqrtf(fmaxf(var, 0.f) + 1e-12f);
        #pragma unroll
        for (int j = 0; j < 6; j++) {
            int c = j * 32 + lane;
            out[(size_t)(m0 + r) * DD + c] = (v[j] - mu) * rs * lng[c] + lnb[c];
        }
    }
}

// =====================================================================================
extern "C" void kernel_launch(void* const* d_in, const int* in_sizes, int n_in,
                              void* d_out, int out_size)
{
    const float* x    = (const float*)d_in[0];
    const float* mask0= (const float*)d_in[1];
    const float* Wq   = (const float*)d_in[2];
    const float* bq   = (const float*)d_in[3];
    const float* Wk   = (const float*)d_in[4];
    const float* bk   = (const float*)d_in[5];
    const float* Wv   = (const float*)d_in[6];
    const float* bv   = (const float*)d_in[7];
    const float* Wo   = (const float*)d_in[8];
    const float* bo   = (const float*)d_in[9];
    const float* lng  = (const float*)d_in[10];
    const float* lnb  = (const float*)d_in[11];
    float* out = (float*)d_out;

    cudaFuncSetAttribute(k_qkv, cudaFuncAttributeMaxDynamicSharedMemorySize, 114688);
    cudaFuncSetAttribute(k_out, cudaFuncAttributeMaxDynamicSharedMemorySize, 114688);

    k_split_w<<<144, 256>>>(Wq, Wk, Wv, Wo);
    k_split_x<<<(MTOT * 48) / 256, 256>>>(x);
    k_qkv<<<dim3(MTOT / 64, 3, 1), 256, 114688>>>(bq, bk, bv);
    k_attn<<<(MTOT * NH) / 256, 256>>>(mask0);
    k_out<<<MTOT / 64, 256, 114688>>>(x, bo, lng, lnb, out);
}